// round 14
// baseline (speedup 1.0000x reference)
#include <cuda_runtime.h>
#include <cuda_fp16.h>
#include <stdint.h>
#include <math.h>

// Problem constants (fixed by setup_inputs)
#define D        128
#define GMAXX    256
#define NMAXX    50048
#define EMAXX    1600000
#define BN_EPS   1e-5f

// ---------------- scratch (device globals; no allocation allowed) ----------------
__device__ float  g_hA[NMAXX * D];
__device__ float  g_hB[NMAXX * D];
__device__ __half g_hh[NMAXX * D];   // fp16 mirror of current h (GEMM A input)
__device__ __half g_zh[NMAXX * D];   // fp16 z (gather source)
__device__ float  g_agg[NMAXX * D];
__device__ float  g_el[NMAXX * 8];
__device__ float  g_er[NMAXX * 8];
__device__ uint2  g_bperm[4096];     // B fragments: [kt(8)][nt(16)][lane(32)] -> {b0,b1}
__device__ float  g_bnsum[D];
__device__ float  g_bnsq[D];
__device__ float  g_bnscale[D];
__device__ float  g_bnshift[D];
__device__ float  g_gsum[GMAXX * D];
__device__ int    g_gcnt[GMAXX];
// CSR scratch
__device__ int    g_cnt[NMAXX];
__device__ int    g_rowptr[NMAXX + 1];
__device__ int    g_cursor[NMAXX];
__device__ int    g_srcs[EMAXX];

// ---------------- CSR build ----------------
__global__ void k_zero_cnt(int N) {
    int i = blockIdx.x * blockDim.x + threadIdx.x;
    if (i < N) g_cnt[i] = 0;
}

__global__ void k_hist(const int* __restrict__ dst, int E) {
    int e = blockIdx.x * blockDim.x + threadIdx.x;
    if (e < E) atomicAdd(&g_cnt[dst[e]], 1);
}

__global__ void k_scan(int N, int E) {
    __shared__ int warp_sums[32];
    __shared__ int s_carry;
    int t = threadIdx.x;          // 1024 threads
    int lane = t & 31, wid = t >> 5;
    if (t == 0) s_carry = 0;
    __syncthreads();
    for (int base = 0; base < N; base += 1024) {
        int i = base + t;
        int v = (i < N) ? g_cnt[i] : 0;
        int x = v;
#pragma unroll
        for (int off = 1; off < 32; off <<= 1) {
            int y = __shfl_up_sync(0xffffffffu, x, off);
            if (lane >= off) x += y;
        }
        if (lane == 31) warp_sums[wid] = x;
        __syncthreads();
        if (wid == 0) {
            int w = warp_sums[lane];
#pragma unroll
            for (int off = 1; off < 32; off <<= 1) {
                int y = __shfl_up_sync(0xffffffffu, w, off);
                if (lane >= off) w += y;
            }
            warp_sums[lane] = w;
        }
        __syncthreads();
        int incl = x + (wid > 0 ? warp_sums[wid - 1] : 0);
        int excl = incl - v + s_carry;
        if (i < N) { g_rowptr[i] = excl; g_cursor[i] = excl; }
        __syncthreads();
        if (t == 1023) s_carry += incl;
        __syncthreads();
    }
    if (t == 0) g_rowptr[N] = E;
}

__global__ void k_scatter(const int* __restrict__ src, const int* __restrict__ dst, int E) {
    int e = blockIdx.x * blockDim.x + threadIdx.x;
    if (e >= E) return;
    int d = dst[e];
    int pos = atomicAdd(&g_cursor[d], 1);
    g_srcs[pos] = src[e];
}

// ---------------- misc ----------------
// finalize BN into per-channel scale/shift (used by fused readout)
__global__ void k_bnfin(const float* __restrict__ gam, const float* __restrict__ bet, float invN) {
    int c = threadIdx.x;
    float mu = g_bnsum[c] * invN;
    float var = g_bnsq[c] * invN - mu * mu;
    float sc = gam[c] * rsqrtf(var + BN_EPS);
    g_bnscale[c] = sc;
    g_bnshift[c] = bet[c] - mu * sc;
}

__global__ void k_zero_readout() {
    int i = blockIdx.x * blockDim.x + threadIdx.x;
    if (i < GMAXX * D) g_gsum[i] = 0.f;
    if (i < GMAXX) g_gcnt[i] = 0;
}

// fp32 -> fp16 conversion (vectorized), count = elements/4
__global__ void k_f2h(const float* __restrict__ in, __half* __restrict__ out, int n4) {
    int i = blockIdx.x * blockDim.x + threadIdx.x;
    if (i >= n4) return;
    float4 v = ((const float4*)in)[i];
    __half2 h0 = __floats2half2_rn(v.x, v.y);
    __half2 h1 = __floats2half2_rn(v.z, v.w);
    uint2 u;
    u.x = *(uint32_t*)&h0; u.y = *(uint32_t*)&h1;
    ((uint2*)out)[i] = u;
}

// ---------------- B fragment pre-permute (also zeroes BN accumulators) -------------
// mode 0: W row-major [k*128+n] (emb_W, fcW_last)
// mode 1: fcW layer [h][d][o]: W[((n>>4)*128 + k)*16 + (n&15)]
__global__ void k_prepB(const float* __restrict__ W, int mode) {
    int i = blockIdx.x * blockDim.x + threadIdx.x;
    if (blockIdx.x == 0 && threadIdx.x < 128) {
        g_bnsum[threadIdx.x] = 0.f;
        g_bnsq[threadIdx.x] = 0.f;
    }
    if (i >= 4096) return;
    int lane = i & 31, nt = (i >> 5) & 15, kt = i >> 9;
    int gid = lane >> 2, tig = lane & 3;
    int n = nt * 8 + gid;
    int k0 = kt * 16 + tig * 2;
    float w0, w1, w2, w3;
    if (mode) {
        const float* base = W + ((n >> 4) * 128) * 16 + (n & 15);
        w0 = base[(k0    ) * 16]; w1 = base[(k0 + 1) * 16];
        w2 = base[(k0 + 8) * 16]; w3 = base[(k0 + 9) * 16];
    } else {
        w0 = W[(k0    ) * 128 + n]; w1 = W[(k0 + 1) * 128 + n];
        w2 = W[(k0 + 8) * 128 + n]; w3 = W[(k0 + 9) * 128 + n];
    }
    __half2 b0 = __floats2half2_rn(w0, w1);
    __half2 b1 = __floats2half2_rn(w2, w3);
    uint2 u; u.x = *(uint32_t*)&b0; u.y = *(uint32_t*)&b1;
    g_bperm[i] = u;
}

// ---------------- tensor-core GEMM: C[N,128] = A[N,128] * B[128,128] ----------------
__device__ __forceinline__ void mma16816(float* c, uint32_t a0, uint32_t a1,
                                         uint32_t a2, uint32_t a3,
                                         uint32_t b0, uint32_t b1) {
    asm("mma.sync.aligned.m16n8k16.row.col.f32.f16.f16.f32 "
        "{%0,%1,%2,%3}, {%4,%5,%6,%7}, {%8,%9}, {%0,%1,%2,%3};"
        : "+f"(c[0]), "+f"(c[1]), "+f"(c[2]), "+f"(c[3])
        : "r"(a0), "r"(a1), "r"(a2), "r"(a3), "r"(b0), "r"(b1));
}

__device__ __forceinline__ float elux(float x) {
    return x > 0.f ? x : expm1f(x);
}

template<bool BIAS, bool STF32, bool STH, bool ATTN, int H>
__global__ void __launch_bounds__(256) k_gemm16(
    const __half* __restrict__ Ah, float* __restrict__ Cf, __half* __restrict__ Ch,
    const float* __restrict__ bias,
    const float* __restrict__ aSl, const float* __restrict__ aDl, int N)
{
    int lane = threadIdx.x & 31, wid = threadIdx.x >> 5;
    int row0 = blockIdx.x * 128 + wid * 16;
    int gid = lane >> 2, tig = lane & 3;
    int rA = row0 + gid, rB = rA + 8;
    int rAc = rA < N ? rA : N - 1;
    int rBc = rB < N ? rB : N - 1;

    float acc[16][4];
#pragma unroll
    for (int nt = 0; nt < 16; nt++)
#pragma unroll
        for (int q = 0; q < 4; q++) acc[nt][q] = 0.f;

#pragma unroll
    for (int kt = 0; kt < 8; kt++) {
        size_t kA = (size_t)rAc * D + kt * 16 + tig * 2;
        size_t kB = (size_t)rBc * D + kt * 16 + tig * 2;
        uint32_t a0 = *(const uint32_t*)(Ah + kA);
        uint32_t a1 = *(const uint32_t*)(Ah + kB);
        uint32_t a2 = *(const uint32_t*)(Ah + kA + 8);
        uint32_t a3 = *(const uint32_t*)(Ah + kB + 8);
#pragma unroll
        for (int nt = 0; nt < 16; nt++) {
            uint2 b = g_bperm[(kt * 16 + nt) * 32 + lane];
            mma16816(acc[nt], a0, a1, a2, a3, b.x, b.y);
        }
    }

    if (BIAS) {
#pragma unroll
        for (int nt = 0; nt < 16; nt++) {
            float2 bv = *(const float2*)(bias + nt * 8 + tig * 2);
            acc[nt][0] += bv.x; acc[nt][1] += bv.y;
            acc[nt][2] += bv.x; acc[nt][3] += bv.y;
        }
    }

    if (ATTN) {
#pragma unroll
        for (int h = 0; h < (H == 8 ? 8 : 1); h++) {
            float elA = 0.f, erA = 0.f, elB = 0.f, erB = 0.f;
            const int nt0 = (H == 8) ? 2 * h : 0;
            const int ntn = (H == 8) ? 2 : 16;
#pragma unroll
            for (int q = 0; q < ntn; q++) {
                int nt = nt0 + q;
                int col = nt * 8 + tig * 2;
                float2 s2 = *(const float2*)(aSl + col);
                float2 d2 = *(const float2*)(aDl + col);
                elA += acc[nt][0] * s2.x + acc[nt][1] * s2.y;
                erA += acc[nt][0] * d2.x + acc[nt][1] * d2.y;
                elB += acc[nt][2] * s2.x + acc[nt][3] * s2.y;
                erB += acc[nt][2] * d2.x + acc[nt][3] * d2.y;
            }
            elA += __shfl_xor_sync(0xffffffffu, elA, 1); elA += __shfl_xor_sync(0xffffffffu, elA, 2);
            erA += __shfl_xor_sync(0xffffffffu, erA, 1); erA += __shfl_xor_sync(0xffffffffu, erA, 2);
            elB += __shfl_xor_sync(0xffffffffu, elB, 1); elB += __shfl_xor_sync(0xffffffffu, elB, 2);
            erB += __shfl_xor_sync(0xffffffffu, erB, 1); erB += __shfl_xor_sync(0xffffffffu, erB, 2);
            if (tig == 0) {
                if (rA < N) { g_el[rA * H + h] = elA; g_er[rA * H + h] = erA; }
                if (rB < N) { g_el[rB * H + h] = elB; g_er[rB * H + h] = erB; }
            }
        }
    }

#pragma unroll
    for (int nt = 0; nt < 16; nt++) {
        int col = nt * 8 + tig * 2;
        if (rA < N) {
            if (STF32) *(float2*)(Cf + (size_t)rA * D + col) = make_float2(acc[nt][0], acc[nt][1]);
            if (STH) {
                __half2 hv = __floats2half2_rn(acc[nt][0], acc[nt][1]);
                *(__half2*)(Ch + (size_t)rA * D + col) = hv;
            }
        }
        if (rB < N) {
            if (STF32) *(float2*)(Cf + (size_t)rB * D + col) = make_float2(acc[nt][2], acc[nt][3]);
            if (STH) {
                __half2 hv = __floats2half2_rn(acc[nt][2], acc[nt][3]);
                *(__half2*)(Ch + (size_t)rB * D + col) = hv;
            }
        }
    }
}

// ---------------- fused node-centric aggregation -----------------------------------
// Pair-processing: each warp = 2 groups of 16 lanes; group g handles edges j+2t+g.
// Each lane loads a uint4 (8 halfs = 8 columns) of the z row. fp32 accumulation.
template<int H>
__global__ void __launch_bounds__(256) k_nodeagg(const float* __restrict__ snorm, int N) {
    int lane = threadIdx.x & 31;
    int wid  = threadIdx.x >> 5;           // 0..7
    int gw   = blockIdx.x * 8 + wid;
    int nwarps = gridDim.x * 8;
    int grp  = lane >> 4;                  // 0/1: which edge of the pair
    int L    = lane & 15;                  // column lane: halfs [8L..8L+7]
    int hh   = (H == 8) ? (L >> 1) : 0;

    float bs0 = 0.f, bs1 = 0.f, bs2 = 0.f, bs3 = 0.f;   // BN partials, cols 8L+4g+q
    float bq0 = 0.f, bq1 = 0.f, bq2 = 0.f, bq3 = 0.f;

    for (int n = gw; n < N; n += nwarps) {
        float ern = g_er[n * H + hh];
        int j0 = g_rowptr[n], j1 = g_rowptr[n + 1];
        float dnm = 0.f;
        float a0 = 0.f, a1 = 0.f, a2 = 0.f, a3 = 0.f;
        float a4 = 0.f, a5 = 0.f, a6 = 0.f, a7 = 0.f;

        for (int j = j0; j < j1; j += 8) {
            int c = j1 - j; if (c > 8) c = 8;
            int ss[4]; float ee[4]; uint4 zz[4];
#pragma unroll
            for (int t = 0; t < 4; t++) {
                int idx = 2 * t + grp;
                if (idx < c) ss[t] = __ldg(&g_srcs[j + idx]);
            }
#pragma unroll
            for (int t = 0; t < 4; t++) {
                int idx = 2 * t + grp;
                if (idx < c) {
                    ee[t] = __ldg(&g_el[ss[t] * H + hh]);
                    zz[t] = __ldg((const uint4*)(g_zh + (size_t)ss[t] * D) + L);
                }
            }
#pragma unroll
            for (int t = 0; t < 4; t++) {
                int idx = 2 * t + grp;
                if (idx < c) {
                    float e = ee[t] + ern;
                    e = fmaxf(e, 0.01f * e);        // leaky_relu
                    float w = __expf(e);            // no-max softmax (fp32 range OK)
                    dnm += w;
                    __half2* hz = (__half2*)&zz[t];
                    float2 f0 = __half22float2(hz[0]);
                    float2 f1 = __half22float2(hz[1]);
                    float2 f2 = __half22float2(hz[2]);
                    float2 f3 = __half22float2(hz[3]);
                    a0 = fmaf(w, f0.x, a0); a1 = fmaf(w, f0.y, a1);
                    a2 = fmaf(w, f1.x, a2); a3 = fmaf(w, f1.y, a3);
                    a4 = fmaf(w, f2.x, a4); a5 = fmaf(w, f2.y, a5);
                    a6 = fmaf(w, f3.x, a6); a7 = fmaf(w, f3.y, a7);
                }
            }
        }
        // combine the two 16-lane groups (lane L <-> lane L+16 hold same columns)
        dnm += __shfl_xor_sync(0xffffffffu, dnm, 16);
        a0 += __shfl_xor_sync(0xffffffffu, a0, 16);
        a1 += __shfl_xor_sync(0xffffffffu, a1, 16);
        a2 += __shfl_xor_sync(0xffffffffu, a2, 16);
        a3 += __shfl_xor_sync(0xffffffffu, a3, 16);
        a4 += __shfl_xor_sync(0xffffffffu, a4, 16);
        a5 += __shfl_xor_sync(0xffffffffu, a5, 16);
        a6 += __shfl_xor_sync(0xffffffffu, a6, 16);
        a7 += __shfl_xor_sync(0xffffffffu, a7, 16);

        float inv = (dnm > 0.f) ? (snorm[n] / dnm) : 0.f;
        a0 *= inv; a1 *= inv; a2 *= inv; a3 *= inv;
        a4 *= inv; a5 *= inv; a6 *= inv; a7 *= inv;

        // store: lane (L, grp) writes float4 of cols 8L+4*grp .. +3
        float4* dst = (float4*)(g_agg + (size_t)n * D);
        float4 v = (grp == 0) ? make_float4(a0, a1, a2, a3)
                              : make_float4(a4, a5, a6, a7);
        dst[L * 2 + grp] = v;
        bs0 += v.x; bs1 += v.y; bs2 += v.z; bs3 += v.w;
        bq0 += v.x * v.x; bq1 += v.y * v.y; bq2 += v.z * v.z; bq3 += v.w * v.w;
    }

    __shared__ float sS[128], sQ[128];
    if (threadIdx.x < 128) { sS[threadIdx.x] = 0.f; sQ[threadIdx.x] = 0.f; }
    __syncthreads();
    int c0 = L * 8 + grp * 4;
    atomicAdd(&sS[c0 + 0], bs0); atomicAdd(&sQ[c0 + 0], bq0);
    atomicAdd(&sS[c0 + 1], bs1); atomicAdd(&sQ[c0 + 1], bq1);
    atomicAdd(&sS[c0 + 2], bs2); atomicAdd(&sQ[c0 + 2], bq2);
    atomicAdd(&sS[c0 + 3], bs3); atomicAdd(&sQ[c0 + 3], bq3);
    __syncthreads();
    if (threadIdx.x < 128) {
        atomicAdd(&g_bnsum[threadIdx.x], sS[threadIdx.x]);
        atomicAdd(&g_bnsq[threadIdx.x], sQ[threadIdx.x]);
    }
}

// ---------------- BN apply + ELU + residual (+ fp16 mirror for next GEMM) ----------
__global__ void k_apply(const float* __restrict__ hin, float* __restrict__ hout,
                        const float* __restrict__ gam, const float* __restrict__ bet, int N) {
    int i = blockIdx.x * blockDim.x + threadIdx.x;
    if (i >= N * D) return;
    int c = i & 127;
    float invN = 1.f / (float)N;
    float mu = g_bnsum[c] * invN;
    float var = g_bnsq[c] * invN - mu * mu;
    float x = (g_agg[i] - mu) * rsqrtf(var + BN_EPS) * gam[c] + bet[c];
    float y = x > 0.f ? x : expm1f(x);
    float r = hin[i] + y;
    hout[i] = r;
    g_hh[i] = __float2half(r);
}

// ---------------- readout with fused final BN apply + ELU + residual ----------------
__global__ void k_readout(const float* __restrict__ hin, const int* __restrict__ gid, int N) {
    int c = threadIdx.x; // 128
    float sc = g_bnscale[c], sh = g_bnshift[c];
    int chunk = (N + gridDim.x - 1) / gridDim.x;
    int n0 = blockIdx.x * chunk;
    int n1 = n0 + chunk; if (n1 > N) n1 = N;
    float acc = 0.f; int gcur = -1, cnt = 0;
    for (int n = n0; n < n1; n++) {
        int g = gid[n];
        if (g != gcur) {
            if (gcur >= 0) {
                atomicAdd(&g_gsum[gcur * D + c], acc);
                if (c == 0) atomicAdd(&g_gcnt[gcur], cnt);
            }
            acc = 0.f; cnt = 0; gcur = g;
        }
        float v = hin[(size_t)n * D + c] + elux(fmaf(g_agg[(size_t)n * D + c], sc, sh));
        acc += v; cnt++;
    }
    if (gcur >= 0) {
        atomicAdd(&g_gsum[gcur * D + c], acc);
        if (c == 0) atomicAdd(&g_gcnt[gcur], cnt);
    }
}

// ---------------- MLP readout: 128 -> 64 -> 32 -> 10 per graph ----------------
__global__ void k_mlp(const float* __restrict__ w1, const float* __restrict__ b1,
                      const float* __restrict__ w2, const float* __restrict__ b2,
                      const float* __restrict__ w3, const float* __restrict__ b3,
                      float* __restrict__ out) {
    int g = blockIdx.x, t = threadIdx.x; // 128 threads
    __shared__ float sh[128], s1[64], s2[32];
    float cnt = (float)g_gcnt[g]; if (cnt < 1.f) cnt = 1.f;
    sh[t] = g_gsum[g * D + t] / cnt;
    __syncthreads();
    if (t < 64) {
        float a = b1[t];
        for (int k = 0; k < 128; k++) a += sh[k] * w1[k * 64 + t];
        s1[t] = a > 0.f ? a : 0.f;
    }
    __syncthreads();
    if (t < 32) {
        float a = b2[t];
        for (int k = 0; k < 64; k++) a += s1[k] * w2[k * 32 + t];
        s2[t] = a > 0.f ? a : 0.f;
    }
    __syncthreads();
    if (t < 10) {
        float a = b3[t];
        for (int k = 0; k < 32; k++) a += s2[k] * w3[k * 10 + t];
        out[g * 10 + t] = a;
    }
}

// ---------------- host orchestration ----------------
static float* symf(const void* s) { void* p = nullptr; cudaGetSymbolAddress(&p, s); return (float*)p; }
static __half* symh(const void* s) { void* p = nullptr; cudaGetSymbolAddress(&p, s); return (__half*)p; }

extern "C" void kernel_launch(void* const* d_in, const int* in_sizes, int n_in,
                              void* d_out, int out_size) {
    const float* nodes_feat = (const float*)d_in[0];
    const float* snorm      = (const float*)d_in[1];
    const float* emb_W      = (const float*)d_in[2];
    const float* emb_b      = (const float*)d_in[3];
    const float* fcW        = (const float*)d_in[4];
    const float* aS         = (const float*)d_in[5];
    const float* aD         = (const float*)d_in[6];
    const float* gamma      = (const float*)d_in[7];
    const float* beta       = (const float*)d_in[8];
    const float* fcW_last   = (const float*)d_in[9];
    const float* aS_last    = (const float*)d_in[10];
    const float* aD_last    = (const float*)d_in[11];
    const float* g_last     = (const float*)d_in[12];
    const float* b_last     = (const float*)d_in[13];
    const float* w1 = (const float*)d_in[14]; const float* b1 = (const float*)d_in[15];
    const float* w2 = (const float*)d_in[16]; const float* b2 = (const float*)d_in[17];
    const float* w3 = (const float*)d_in[18]; const float* b3 = (const float*)d_in[19];
    const int* src = (const int*)d_in[20];
    const int* dst = (const int*)d_in[21];
    const int* gid = (const int*)d_in[22];

    int N = in_sizes[0] / D;
    int E = in_sizes[20];
    float* out = (float*)d_out;
    float invN = 1.f / (float)N;

    float*  hA = symf(g_hA);
    float*  hB = symf(g_hB);
    __half* hh = symh(g_hh);
    __half* zh = symh(g_zh);

    int gblocks = (N + 127) / 128;
    int nd_blocks = (N * D + 255) / 256;
    int e_blocks = (E + 255) / 256;
    int f2h_blocks = (N * D / 4 + 255) / 256;

    // Build CSR (dst fixed for the whole forward pass)
    k_zero_cnt<<<(N + 255) / 256, 256>>>(N);
    k_hist<<<e_blocks, 256>>>(dst, E);
    k_scan<<<1, 1024>>>(N, E);
    k_scatter<<<e_blocks, 256>>>(src, dst, E);

    // embedding: A = fp16(nodes_feat) in hh; epilogue writes fp32 hA AND fp16 hh
    // (aliasing Ah==Ch is safe: each warp reads only its own 16-row strip before
    //  its epilogue stores; no cross-warp row sharing).
    k_f2h<<<f2h_blocks, 256>>>(nodes_feat, hh, N * D / 4);
    k_prepB<<<16, 256>>>(emb_W, 0);
    k_gemm16<true, true, true, false, 8><<<gblocks, 256>>>(hh, hA, hh, emb_b,
                                                           nullptr, nullptr, N);

    const float* hin = hA;
    float* hout = hB;

    // 3 multi-head layers (H=8, O=16)
    for (int l = 0; l < 3; l++) {
        k_prepB<<<16, 256>>>(fcW + (size_t)l * 8 * D * 16, 1);   // also zeroes BN sums
        k_gemm16<false, false, true, true, 8><<<gblocks, 256>>>(hh, nullptr, zh, nullptr,
                                                                aS + l * 128, aD + l * 128, N);
        k_nodeagg<8><<<592, 256>>>(snorm, N);
        k_apply<<<nd_blocks, 256>>>(hin, hout, gamma + l * 128, beta + l * 128, N);
        const float* tmp = hin; hin = hout; hout = (float*)tmp;
    }

    // last layer (H=1, O=128): fused 128-wide attn logits, fp16 z only.
    // Final BN/ELU/residual is NOT materialized — folded into k_readout.
    {
        k_prepB<<<16, 256>>>(fcW_last, 0);                       // also zeroes BN sums
        k_gemm16<false, false, true, true, 1><<<gblocks, 256>>>(hh, nullptr, zh, nullptr,
                                                                aS_last, aD_last, N);
        k_nodeagg<1><<<592, 256>>>(snorm, N);
        k_bnfin<<<1, 128>>>(g_last, b_last, invN);
    }

    // readout: fused final apply (hin = layer-3 output) + run-length segment sum
    k_zero_readout<<<(GMAXX * D + 255) / 256, 256>>>();
    k_readout<<<512, 128>>>(hin, gid, N);
    k_mlp<<<GMAXX, 128>>>(w1, b1, w2, b2, w3, b3, out);
}

// round 15
// speedup vs baseline: 1.5058x; 1.5058x over previous
#include <cuda_runtime.h>
#include <cuda_fp16.h>
#include <stdint.h>
#include <math.h>

// Problem constants (fixed by setup_inputs)
#define D        128
#define GMAXX    256
#define NMAXX    50048
#define EMAXX    1600000
#define BN_EPS   1e-5f

// ---------------- scratch (device globals; no allocation allowed) ----------------
__device__ float  g_hA[NMAXX * D];
__device__ float  g_hB[NMAXX * D];
__device__ __half g_hh[NMAXX * D];   // fp16 mirror of current h (GEMM A input)
__device__ __half g_zh[NMAXX * D];   // fp16 z (gather source)
__device__ float  g_agg[NMAXX * D];
__device__ float  g_el[NMAXX * 8];
__device__ float  g_er[NMAXX * 8];
__device__ uint2  g_bperm[4096];     // B fragments: [kt(8)][nt(16)][lane(32)] -> {b0,b1}
__device__ float  g_bnsum[D];
__device__ float  g_bnsq[D];
__device__ float  g_bnscale[D];
__device__ float  g_bnshift[D];
__device__ float  g_gsum[GMAXX * D];
__device__ int    g_gcnt[GMAXX];
// CSR scratch
__device__ int    g_cnt[NMAXX];
__device__ int    g_rowptr[NMAXX + 1];
__device__ int    g_cursor[NMAXX];
__device__ int    g_srcs[EMAXX];

// ---------------- CSR build ----------------
__global__ void k_zero_cnt(int N) {
    int i = blockIdx.x * blockDim.x + threadIdx.x;
    if (i < N) g_cnt[i] = 0;
}

__global__ void k_hist(const int* __restrict__ dst, int E) {
    int i = blockIdx.x * blockDim.x + threadIdx.x;
    int e = i * 4;
    if (e + 3 < E) {
        int4 d4 = *(const int4*)(dst + e);
        atomicAdd(&g_cnt[d4.x], 1);
        atomicAdd(&g_cnt[d4.y], 1);
        atomicAdd(&g_cnt[d4.z], 1);
        atomicAdd(&g_cnt[d4.w], 1);
    } else {
        for (int q = e; q < E; q++) atomicAdd(&g_cnt[dst[q]], 1);
    }
}

__global__ void k_scan(int N, int E) {
    __shared__ int warp_sums[32];
    __shared__ int s_carry;
    int t = threadIdx.x;          // 1024 threads
    int lane = t & 31, wid = t >> 5;
    if (t == 0) s_carry = 0;
    __syncthreads();
    for (int base = 0; base < N; base += 1024) {
        int i = base + t;
        int v = (i < N) ? g_cnt[i] : 0;
        int x = v;
#pragma unroll
        for (int off = 1; off < 32; off <<= 1) {
            int y = __shfl_up_sync(0xffffffffu, x, off);
            if (lane >= off) x += y;
        }
        if (lane == 31) warp_sums[wid] = x;
        __syncthreads();
        if (wid == 0) {
            int w = warp_sums[lane];
#pragma unroll
            for (int off = 1; off < 32; off <<= 1) {
                int y = __shfl_up_sync(0xffffffffu, w, off);
                if (lane >= off) w += y;
            }
            warp_sums[lane] = w;
        }
        __syncthreads();
        int incl = x + (wid > 0 ? warp_sums[wid - 1] : 0);
        int excl = incl - v + s_carry;
        if (i < N) { g_rowptr[i] = excl; g_cursor[i] = excl; }
        __syncthreads();
        if (t == 1023) s_carry += incl;
        __syncthreads();
    }
    if (t == 0) g_rowptr[N] = E;
}

__global__ void k_scatter(const int* __restrict__ src, const int* __restrict__ dst, int E) {
    int e = blockIdx.x * blockDim.x + threadIdx.x;
    if (e >= E) return;
    int d = dst[e];
    int pos = atomicAdd(&g_cursor[d], 1);
    g_srcs[pos] = src[e];
}

// ---------------- misc ----------------
// finalize BN into per-channel scale/shift (used by fused readout)
__global__ void k_bnfin(const float* __restrict__ gam, const float* __restrict__ bet, float invN) {
    int c = threadIdx.x;
    float mu = g_bnsum[c] * invN;
    float var = g_bnsq[c] * invN - mu * mu;
    float sc = gam[c] * rsqrtf(var + BN_EPS);
    g_bnscale[c] = sc;
    g_bnshift[c] = bet[c] - mu * sc;
}

__global__ void k_zero_readout() {
    int i = blockIdx.x * blockDim.x + threadIdx.x;
    if (i < GMAXX * D) g_gsum[i] = 0.f;
    if (i < GMAXX) g_gcnt[i] = 0;
}

// fp32 -> fp16 conversion (vectorized), count = elements/4
__global__ void k_f2h(const float* __restrict__ in, __half* __restrict__ out, int n4) {
    int i = blockIdx.x * blockDim.x + threadIdx.x;
    if (i >= n4) return;
    float4 v = ((const float4*)in)[i];
    __half2 h0 = __floats2half2_rn(v.x, v.y);
    __half2 h1 = __floats2half2_rn(v.z, v.w);
    uint2 u;
    u.x = *(uint32_t*)&h0; u.y = *(uint32_t*)&h1;
    ((uint2*)out)[i] = u;
}

// ---------------- B fragment pre-permute (also zeroes BN accumulators) -------------
// mode 0: W row-major [k*128+n] (emb_W, fcW_last)
// mode 1: fcW layer [h][d][o]: W[((n>>4)*128 + k)*16 + (n&15)]
__global__ void k_prepB(const float* __restrict__ W, int mode) {
    int i = blockIdx.x * blockDim.x + threadIdx.x;
    if (blockIdx.x == 0 && threadIdx.x < 128) {
        g_bnsum[threadIdx.x] = 0.f;
        g_bnsq[threadIdx.x] = 0.f;
    }
    if (i >= 4096) return;
    int lane = i & 31, nt = (i >> 5) & 15, kt = i >> 9;
    int gid = lane >> 2, tig = lane & 3;
    int n = nt * 8 + gid;
    int k0 = kt * 16 + tig * 2;
    float w0, w1, w2, w3;
    if (mode) {
        const float* base = W + ((n >> 4) * 128) * 16 + (n & 15);
        w0 = base[(k0    ) * 16]; w1 = base[(k0 + 1) * 16];
        w2 = base[(k0 + 8) * 16]; w3 = base[(k0 + 9) * 16];
    } else {
        w0 = W[(k0    ) * 128 + n]; w1 = W[(k0 + 1) * 128 + n];
        w2 = W[(k0 + 8) * 128 + n]; w3 = W[(k0 + 9) * 128 + n];
    }
    __half2 b0 = __floats2half2_rn(w0, w1);
    __half2 b1 = __floats2half2_rn(w2, w3);
    uint2 u; u.x = *(uint32_t*)&b0; u.y = *(uint32_t*)&b1;
    g_bperm[i] = u;
}

// ---------------- tensor-core GEMM: C[N,128] = A[N,128] * B[128,128] ----------------
__device__ __forceinline__ void mma16816(float* c, uint32_t a0, uint32_t a1,
                                         uint32_t a2, uint32_t a3,
                                         uint32_t b0, uint32_t b1) {
    asm("mma.sync.aligned.m16n8k16.row.col.f32.f16.f16.f32 "
        "{%0,%1,%2,%3}, {%4,%5,%6,%7}, {%8,%9}, {%0,%1,%2,%3};"
        : "+f"(c[0]), "+f"(c[1]), "+f"(c[2]), "+f"(c[3])
        : "r"(a0), "r"(a1), "r"(a2), "r"(a3), "r"(b0), "r"(b1));
}

__device__ __forceinline__ float elux(float x) {
    return x > 0.f ? x : expm1f(x);
}

template<bool BIAS, bool STF32, bool STH, bool ATTN, int H>
__global__ void __launch_bounds__(256) k_gemm16(
    const __half* __restrict__ Ah, float* __restrict__ Cf, __half* __restrict__ Ch,
    const float* __restrict__ bias,
    const float* __restrict__ aSl, const float* __restrict__ aDl, int N)
{
    int lane = threadIdx.x & 31, wid = threadIdx.x >> 5;
    int row0 = blockIdx.x * 128 + wid * 16;
    int gid = lane >> 2, tig = lane & 3;
    int rA = row0 + gid, rB = rA + 8;
    int rAc = rA < N ? rA : N - 1;
    int rBc = rB < N ? rB : N - 1;

    float acc[16][4];
#pragma unroll
    for (int nt = 0; nt < 16; nt++)
#pragma unroll
        for (int q = 0; q < 4; q++) acc[nt][q] = 0.f;

#pragma unroll
    for (int kt = 0; kt < 8; kt++) {
        size_t kA = (size_t)rAc * D + kt * 16 + tig * 2;
        size_t kB = (size_t)rBc * D + kt * 16 + tig * 2;
        uint32_t a0 = *(const uint32_t*)(Ah + kA);
        uint32_t a1 = *(const uint32_t*)(Ah + kB);
        uint32_t a2 = *(const uint32_t*)(Ah + kA + 8);
        uint32_t a3 = *(const uint32_t*)(Ah + kB + 8);
#pragma unroll
        for (int nt = 0; nt < 16; nt++) {
            uint2 b = g_bperm[(kt * 16 + nt) * 32 + lane];
            mma16816(acc[nt], a0, a1, a2, a3, b.x, b.y);
        }
    }

    if (BIAS) {
#pragma unroll
        for (int nt = 0; nt < 16; nt++) {
            float2 bv = *(const float2*)(bias + nt * 8 + tig * 2);
            acc[nt][0] += bv.x; acc[nt][1] += bv.y;
            acc[nt][2] += bv.x; acc[nt][3] += bv.y;
        }
    }

    if (ATTN) {
#pragma unroll
        for (int h = 0; h < (H == 8 ? 8 : 1); h++) {
            float elA = 0.f, erA = 0.f, elB = 0.f, erB = 0.f;
            const int nt0 = (H == 8) ? 2 * h : 0;
            const int ntn = (H == 8) ? 2 : 16;
#pragma unroll
            for (int q = 0; q < ntn; q++) {
                int nt = nt0 + q;
                int col = nt * 8 + tig * 2;
                float2 s2 = *(const float2*)(aSl + col);
                float2 d2 = *(const float2*)(aDl + col);
                elA += acc[nt][0] * s2.x + acc[nt][1] * s2.y;
                erA += acc[nt][0] * d2.x + acc[nt][1] * d2.y;
                elB += acc[nt][2] * s2.x + acc[nt][3] * s2.y;
                erB += acc[nt][2] * d2.x + acc[nt][3] * d2.y;
            }
            elA += __shfl_xor_sync(0xffffffffu, elA, 1); elA += __shfl_xor_sync(0xffffffffu, elA, 2);
            erA += __shfl_xor_sync(0xffffffffu, erA, 1); erA += __shfl_xor_sync(0xffffffffu, erA, 2);
            elB += __shfl_xor_sync(0xffffffffu, elB, 1); elB += __shfl_xor_sync(0xffffffffu, elB, 2);
            erB += __shfl_xor_sync(0xffffffffu, erB, 1); erB += __shfl_xor_sync(0xffffffffu, erB, 2);
            if (tig == 0) {
                if (rA < N) { g_el[rA * H + h] = elA; g_er[rA * H + h] = erA; }
                if (rB < N) { g_el[rB * H + h] = elB; g_er[rB * H + h] = erB; }
            }
        }
    }

#pragma unroll
    for (int nt = 0; nt < 16; nt++) {
        int col = nt * 8 + tig * 2;
        if (rA < N) {
            if (STF32) *(float2*)(Cf + (size_t)rA * D + col) = make_float2(acc[nt][0], acc[nt][1]);
            if (STH) {
                __half2 hv = __floats2half2_rn(acc[nt][0], acc[nt][1]);
                *(__half2*)(Ch + (size_t)rA * D + col) = hv;
            }
        }
        if (rB < N) {
            if (STF32) *(float2*)(Cf + (size_t)rB * D + col) = make_float2(acc[nt][2], acc[nt][3]);
            if (STH) {
                __half2 hv = __floats2half2_rn(acc[nt][2], acc[nt][3]);
                *(__half2*)(Ch + (size_t)rB * D + col) = hv;
            }
        }
    }
}

// ---------------- fused node-centric aggregation -----------------------------------
// Pair-processing: each warp = 2 groups of 16 lanes; group g handles edges j+2t+g.
// Each lane loads a uint4 (8 halfs = 8 columns) of the z row. fp32 accumulation.
template<int H>
__global__ void __launch_bounds__(256) k_nodeagg(const float* __restrict__ snorm, int N) {
    int lane = threadIdx.x & 31;
    int wid  = threadIdx.x >> 5;           // 0..7
    int gw   = blockIdx.x * 8 + wid;
    int nwarps = gridDim.x * 8;
    int grp  = lane >> 4;                  // 0/1: which edge of the pair
    int L    = lane & 15;                  // column lane: halfs [8L..8L+7]
    int hh   = (H == 8) ? (L >> 1) : 0;

    float bs0 = 0.f, bs1 = 0.f, bs2 = 0.f, bs3 = 0.f;   // BN partials, cols 8L+4g+q
    float bq0 = 0.f, bq1 = 0.f, bq2 = 0.f, bq3 = 0.f;

    for (int n = gw; n < N; n += nwarps) {
        float ern = g_er[n * H + hh];
        int j0 = g_rowptr[n], j1 = g_rowptr[n + 1];
        float dnm = 0.f;
        float a0 = 0.f, a1 = 0.f, a2 = 0.f, a3 = 0.f;
        float a4 = 0.f, a5 = 0.f, a6 = 0.f, a7 = 0.f;

        for (int j = j0; j < j1; j += 8) {
            int c = j1 - j; if (c > 8) c = 8;
            int ss[4]; float ee[4]; uint4 zz[4];
#pragma unroll
            for (int t = 0; t < 4; t++) {
                int idx = 2 * t + grp;
                if (idx < c) ss[t] = __ldg(&g_srcs[j + idx]);
            }
#pragma unroll
            for (int t = 0; t < 4; t++) {
                int idx = 2 * t + grp;
                if (idx < c) {
                    ee[t] = __ldg(&g_el[ss[t] * H + hh]);
                    zz[t] = __ldg((const uint4*)(g_zh + (size_t)ss[t] * D) + L);
                }
            }
#pragma unroll
            for (int t = 0; t < 4; t++) {
                int idx = 2 * t + grp;
                if (idx < c) {
                    float e = ee[t] + ern;
                    e = fmaxf(e, 0.01f * e);        // leaky_relu
                    float w = __expf(e);            // no-max softmax (fp32 range OK)
                    dnm += w;
                    __half2* hz = (__half2*)&zz[t];
                    float2 f0 = __half22float2(hz[0]);
                    float2 f1 = __half22float2(hz[1]);
                    float2 f2 = __half22float2(hz[2]);
                    float2 f3 = __half22float2(hz[3]);
                    a0 = fmaf(w, f0.x, a0); a1 = fmaf(w, f0.y, a1);
                    a2 = fmaf(w, f1.x, a2); a3 = fmaf(w, f1.y, a3);
                    a4 = fmaf(w, f2.x, a4); a5 = fmaf(w, f2.y, a5);
                    a6 = fmaf(w, f3.x, a6); a7 = fmaf(w, f3.y, a7);
                }
            }
        }
        // combine the two 16-lane groups (lane L <-> lane L+16 hold same columns)
        dnm += __shfl_xor_sync(0xffffffffu, dnm, 16);
        a0 += __shfl_xor_sync(0xffffffffu, a0, 16);
        a1 += __shfl_xor_sync(0xffffffffu, a1, 16);
        a2 += __shfl_xor_sync(0xffffffffu, a2, 16);
        a3 += __shfl_xor_sync(0xffffffffu, a3, 16);
        a4 += __shfl_xor_sync(0xffffffffu, a4, 16);
        a5 += __shfl_xor_sync(0xffffffffu, a5, 16);
        a6 += __shfl_xor_sync(0xffffffffu, a6, 16);
        a7 += __shfl_xor_sync(0xffffffffu, a7, 16);

        float inv = (dnm > 0.f) ? (snorm[n] / dnm) : 0.f;
        a0 *= inv; a1 *= inv; a2 *= inv; a3 *= inv;
        a4 *= inv; a5 *= inv; a6 *= inv; a7 *= inv;

        // store: lane (L, grp) writes float4 of cols 8L+4*grp .. +3
        float4* dst = (float4*)(g_agg + (size_t)n * D);
        float4 v = (grp == 0) ? make_float4(a0, a1, a2, a3)
                              : make_float4(a4, a5, a6, a7);
        dst[L * 2 + grp] = v;
        bs0 += v.x; bs1 += v.y; bs2 += v.z; bs3 += v.w;
        bq0 += v.x * v.x; bq1 += v.y * v.y; bq2 += v.z * v.z; bq3 += v.w * v.w;
    }

    __shared__ float sS[128], sQ[128];
    if (threadIdx.x < 128) { sS[threadIdx.x] = 0.f; sQ[threadIdx.x] = 0.f; }
    __syncthreads();
    int c0 = L * 8 + grp * 4;
    atomicAdd(&sS[c0 + 0], bs0); atomicAdd(&sQ[c0 + 0], bq0);
    atomicAdd(&sS[c0 + 1], bs1); atomicAdd(&sQ[c0 + 1], bq1);
    atomicAdd(&sS[c0 + 2], bs2); atomicAdd(&sQ[c0 + 2], bq2);
    atomicAdd(&sS[c0 + 3], bs3); atomicAdd(&sQ[c0 + 3], bq3);
    __syncthreads();
    if (threadIdx.x < 128) {
        atomicAdd(&g_bnsum[threadIdx.x], sS[threadIdx.x]);
        atomicAdd(&g_bnsq[threadIdx.x], sQ[threadIdx.x]);
    }
}

// ---------------- BN apply + ELU + residual (+ fp16 mirror), float4-vectorized -----
__global__ void k_apply(const float* __restrict__ hin, float* __restrict__ hout,
                        const float* __restrict__ gam, const float* __restrict__ bet,
                        int N, float invN) {
    int i4 = blockIdx.x * blockDim.x + threadIdx.x;   // one float4 per thread
    if (i4 >= N * (D / 4)) return;
    int c = (i4 & 31) * 4;                            // channel of first element
    float4 g = ((const float4*)g_agg)[i4];
    float4 hi = ((const float4*)hin)[i4];
    float4 r;
    {
        float mu = g_bnsum[c + 0] * invN;
        float var = g_bnsq[c + 0] * invN - mu * mu;
        float x = (g.x - mu) * rsqrtf(var + BN_EPS) * gam[c + 0] + bet[c + 0];
        r.x = hi.x + elux(x);
    }
    {
        float mu = g_bnsum[c + 1] * invN;
        float var = g_bnsq[c + 1] * invN - mu * mu;
        float x = (g.y - mu) * rsqrtf(var + BN_EPS) * gam[c + 1] + bet[c + 1];
        r.y = hi.y + elux(x);
    }
    {
        float mu = g_bnsum[c + 2] * invN;
        float var = g_bnsq[c + 2] * invN - mu * mu;
        float x = (g.z - mu) * rsqrtf(var + BN_EPS) * gam[c + 2] + bet[c + 2];
        r.z = hi.z + elux(x);
    }
    {
        float mu = g_bnsum[c + 3] * invN;
        float var = g_bnsq[c + 3] * invN - mu * mu;
        float x = (g.w - mu) * rsqrtf(var + BN_EPS) * gam[c + 3] + bet[c + 3];
        r.w = hi.w + elux(x);
    }
    ((float4*)hout)[i4] = r;
    __half2 h0 = __floats2half2_rn(r.x, r.y);
    __half2 h1 = __floats2half2_rn(r.z, r.w);
    uint2 u; u.x = *(uint32_t*)&h0; u.y = *(uint32_t*)&h1;
    ((uint2*)g_hh)[i4] = u;
}

// ---------------- readout with fused final BN apply + ELU + residual ----------------
__global__ void k_readout(const float* __restrict__ hin, const int* __restrict__ gid, int N) {
    int c = threadIdx.x; // 128
    float sc = g_bnscale[c], sh = g_bnshift[c];
    int chunk = (N + gridDim.x - 1) / gridDim.x;
    int n0 = blockIdx.x * chunk;
    int n1 = n0 + chunk; if (n1 > N) n1 = N;
    float acc = 0.f; int gcur = -1, cnt = 0;
    for (int n = n0; n < n1; n++) {
        int g = gid[n];
        if (g != gcur) {
            if (gcur >= 0) {
                atomicAdd(&g_gsum[gcur * D + c], acc);
                if (c == 0) atomicAdd(&g_gcnt[gcur], cnt);
            }
            acc = 0.f; cnt = 0; gcur = g;
        }
        float v = hin[(size_t)n * D + c] + elux(fmaf(g_agg[(size_t)n * D + c], sc, sh));
        acc += v; cnt++;
    }
    if (gcur >= 0) {
        atomicAdd(&g_gsum[gcur * D + c], acc);
        if (c == 0) atomicAdd(&g_gcnt[gcur], cnt);
    }
}

// ---------------- MLP readout: 128 -> 64 -> 32 -> 10 per graph ----------------
__global__ void k_mlp(const float* __restrict__ w1, const float* __restrict__ b1,
                      const float* __restrict__ w2, const float* __restrict__ b2,
                      const float* __restrict__ w3, const float* __restrict__ b3,
                      float* __restrict__ out) {
    int g = blockIdx.x, t = threadIdx.x; // 128 threads
    __shared__ float sh[128], s1[64], s2[32];
    float cnt = (float)g_gcnt[g]; if (cnt < 1.f) cnt = 1.f;
    sh[t] = g_gsum[g * D + t] / cnt;
    __syncthreads();
    if (t < 64) {
        float a = b1[t];
        for (int k = 0; k < 128; k++) a += sh[k] * w1[k * 64 + t];
        s1[t] = a > 0.f ? a : 0.f;
    }
    __syncthreads();
    if (t < 32) {
        float a = b2[t];
        for (int k = 0; k < 64; k++) a += s1[k] * w2[k * 32 + t];
        s2[t] = a > 0.f ? a : 0.f;
    }
    __syncthreads();
    if (t < 10) {
        float a = b3[t];
        for (int k = 0; k < 32; k++) a += s2[k] * w3[k * 10 + t];
        out[g * 10 + t] = a;
    }
}

// ---------------- host orchestration ----------------
static float* symf(const void* s) { void* p = nullptr; cudaGetSymbolAddress(&p, s); return (float*)p; }
static __half* symh(const void* s) { void* p = nullptr; cudaGetSymbolAddress(&p, s); return (__half*)p; }

extern "C" void kernel_launch(void* const* d_in, const int* in_sizes, int n_in,
                              void* d_out, int out_size) {
    const float* nodes_feat = (const float*)d_in[0];
    const float* snorm      = (const float*)d_in[1];
    const float* emb_W      = (const float*)d_in[2];
    const float* emb_b      = (const float*)d_in[3];
    const float* fcW        = (const float*)d_in[4];
    const float* aS         = (const float*)d_in[5];
    const float* aD         = (const float*)d_in[6];
    const float* gamma      = (const float*)d_in[7];
    const float* beta       = (const float*)d_in[8];
    const float* fcW_last   = (const float*)d_in[9];
    const float* aS_last    = (const float*)d_in[10];
    const float* aD_last    = (const float*)d_in[11];
    const float* g_last     = (const float*)d_in[12];
    const float* b_last     = (const float*)d_in[13];
    const float* w1 = (const float*)d_in[14]; const float* b1 = (const float*)d_in[15];
    const float* w2 = (const float*)d_in[16]; const float* b2 = (const float*)d_in[17];
    const float* w3 = (const float*)d_in[18]; const float* b3 = (const float*)d_in[19];
    const int* src = (const int*)d_in[20];
    const int* dst = (const int*)d_in[21];
    const int* gid = (const int*)d_in[22];

    int N = in_sizes[0] / D;
    int E = in_sizes[20];
    float* out = (float*)d_out;
    float invN = 1.f / (float)N;

    float*  hA = symf(g_hA);
    float*  hB = symf(g_hB);
    __half* hh = symh(g_hh);
    __half* zh = symh(g_zh);

    int gblocks = (N + 127) / 128;
    int nd4_blocks = (N * (D / 4) + 255) / 256;
    int e_blocks = (E + 255) / 256;
    int e4_blocks = (E + 1023) / 1024;
    int f2h_blocks = (N * D / 4 + 255) / 256;

    // Build CSR (dst fixed for the whole forward pass)
    k_zero_cnt<<<(N + 255) / 256, 256>>>(N);
    k_hist<<<e4_blocks, 256>>>(dst, E);
    k_scan<<<1, 1024>>>(N, E);
    k_scatter<<<e_blocks, 256>>>(src, dst, E);

    // embedding: A = fp16(nodes_feat) in hh; epilogue writes fp32 hA AND fp16 hh
    // (aliasing Ah==Ch is safe: each warp reads only its own 16-row strip before
    //  its epilogue stores; no cross-warp row sharing).
    k_f2h<<<f2h_blocks, 256>>>(nodes_feat, hh, N * D / 4);
    k_prepB<<<16, 256>>>(emb_W, 0);
    k_gemm16<true, true, true, false, 8><<<gblocks, 256>>>(hh, hA, hh, emb_b,
                                                           nullptr, nullptr, N);

    const float* hin = hA;
    float* hout = hB;

    // 3 multi-head layers (H=8, O=16)
    for (int l = 0; l < 3; l++) {
        k_prepB<<<16, 256>>>(fcW + (size_t)l * 8 * D * 16, 1);   // also zeroes BN sums
        k_gemm16<false, false, true, true, 8><<<gblocks, 256>>>(hh, nullptr, zh, nullptr,
                                                                aS + l * 128, aD + l * 128, N);
        k_nodeagg<8><<<592, 256>>>(snorm, N);
        k_apply<<<nd4_blocks, 256>>>(hin, hout, gamma + l * 128, beta + l * 128, N, invN);
        const float* tmp = hin; hin = hout; hout = (float*)tmp;
    }

    // last layer (H=1, O=128): fused 128-wide attn logits, fp16 z only.
    // Final BN/ELU/residual is NOT materialized — folded into k_readout.
    {
        k_prepB<<<16, 256>>>(fcW_last, 0);                       // also zeroes BN sums
        k_gemm16<false, false, true, true, 1><<<gblocks, 256>>>(hh, nullptr, zh, nullptr,
                                                                aS_last, aD_last, N);
        k_nodeagg<1><<<592, 256>>>(snorm, N);
        k_bnfin<<<1, 128>>>(g_last, b_last, invN);
    }

    // readout: fused final apply (hin = layer-3 output) + run-length segment sum
    k_zero_readout<<<(GMAXX * D + 255) / 256, 256>>>();
    k_readout<<<512, 128>>>(hin, gid, N);
    k_mlp<<<GMAXX, 128>>>(w1, b1, w2, b2, w3, b3, out);
}